// round 15
// baseline (speedup 1.0000x reference)
#include <cuda_runtime.h>
#include <cuda_fp16.h>
#include <cstdint>

// out = IFFT( D .* FFT( A .* x ) ) per row, C = 4096, complex as (re,im) float pairs.
// A, D scale re/im independently (elementwise).
//
// 256 threads per row, ONE lane per thread (16 points), 64 regs, ~48% occupancy.
// 4096 = 16^3: three radix-16 register stages; two fp16-staged shared exchanges
// per direction (strides 258 / 18, conflict-free). Variable twiddles come from
// k-major GLOBAL tables (filled once per launch by a tiny init kernel):
//   g_T1[k][t]  = w4096^{t(k+1)}  (15 x 256, coalesced LDG.64, L1/L2-resident)
//   g_T2[k][b2] = w256^{b2(k+1)}  (15 x 16)
// Forward direction uses the conjugate via a free operand negation.

#define REV(c) ((((c) & 3) << 2) | ((c) >> 2))

__device__ float2 g_T1[15 * 256];
__device__ float2 g_T2[15 * 16];

#define D4096 1.5339807878856412e-3f   // 2*pi/4096
#define D256  2.4543692606170259e-2f   // 2*pi/256
#define INV_N (1.0f / 4096.0f)

__global__ void afdf_twiddle_init(){
    const int t = threadIdx.x;          // 0..255
    #pragma unroll
    for (int k = 0; k < 15; ++k){
        const float a1 = (float)((k + 1) * t) * D4096;
        g_T1[k * 256 + t] = make_float2(cosf(a1), sinf(a1));
        if (t < 16){
            const float a2 = (float)((k + 1) * t) * D256;
            g_T2[k * 16 + t] = make_float2(cosf(a2), sinf(a2));
        }
    }
}

__device__ __forceinline__ void cmul(float& r, float& i, float wr, float wi){
    float t = i * wi;
    float u = i * wr;
    float nr = fmaf(r, wr, -t);
    i = fmaf(r, wi, u);
    r = nr;
}
template<int DIR> __device__ __forceinline__ void mulj(float& r, float& i){
    float t = r;
    if (DIR < 0){ r = i;  i = -t; }
    else        { r = -i; i = t;  }
}
template<int DIR> __device__ __forceinline__ void cmulc(float& r, float& i, float cr, float ci_f){
    cmul(r, i, cr, (DIR < 0) ? ci_f : -ci_f);
}

#define TC1 0.92387953251128674f
#define TS1 0.38268343236508978f
#define TC2 0.70710678118654752f

template<int DIR>
__device__ __forceinline__ void fft4s(float& r0, float& i0, float& r1, float& i1,
                                      float& r2, float& i2, float& r3, float& i3){
    float t0r = r0 + r2, t0i = i0 + i2;
    float t1r = r0 - r2, t1i = i0 - i2;
    float t2r = r1 + r3, t2i = i1 + i3;
    float t3r, t3i;
    if (DIR < 0){ t3r = i1 - i3; t3i = r3 - r1; }
    else        { t3r = i3 - i1; t3i = r1 - r3; }
    r0 = t0r + t2r; i0 = t0i + t2i;
    r2 = t0r - t2r; i2 = t0i - t2i;
    r1 = t1r + t3r; i1 = t1i + t3i;
    r3 = t1r - t3r; i3 = t1i - t3i;
}

template<int DIR>
__device__ __forceinline__ void fft16_nat(float r[16], float i[16]){
    fft4s<DIR>(r[0],i[0], r[4],i[4], r[8], i[8],  r[12],i[12]);
    fft4s<DIR>(r[1],i[1], r[5],i[5], r[9], i[9],  r[13],i[13]);
    fft4s<DIR>(r[2],i[2], r[6],i[6], r[10],i[10], r[14],i[14]);
    fft4s<DIR>(r[3],i[3], r[7],i[7], r[11],i[11], r[15],i[15]);
    cmulc<DIR>(r[5], i[5],  TC1, -TS1);
    cmulc<DIR>(r[9], i[9],  TC2, -TC2);
    cmulc<DIR>(r[13],i[13], TS1, -TC1);
    cmulc<DIR>(r[6], i[6],  TC2, -TC2);
    mulj<DIR>(r[10],i[10]);
    cmulc<DIR>(r[14],i[14],-TC2, -TC2);
    cmulc<DIR>(r[7], i[7],  TS1, -TC1);
    cmulc<DIR>(r[11],i[11],-TC2, -TC2);
    cmulc<DIR>(r[15],i[15],-TC1,  TS1);
    fft4s<DIR>(r[0], i[0],  r[1], i[1],  r[2], i[2],  r[3], i[3]);
    fft4s<DIR>(r[4], i[4],  r[5], i[5],  r[6], i[6],  r[7], i[7]);
    fft4s<DIR>(r[8], i[8],  r[9], i[9],  r[10],i[10], r[11],i[11]);
    fft4s<DIR>(r[12],i[12], r[13],i[13], r[14],i[14], r[15],i[15]);
}

template<int DIR>
__device__ __forceinline__ void fft16_rev(float r[16], float i[16]){
    fft4s<DIR>(r[0], i[0],  r[1], i[1],  r[2], i[2],  r[3], i[3]);
    fft4s<DIR>(r[4], i[4],  r[5], i[5],  r[6], i[6],  r[7], i[7]);
    fft4s<DIR>(r[8], i[8],  r[9], i[9],  r[10],i[10], r[11],i[11]);
    fft4s<DIR>(r[12],i[12], r[13],i[13], r[14],i[14], r[15],i[15]);
    cmulc<DIR>(r[5], i[5],  TC1, -TS1);
    cmulc<DIR>(r[6], i[6],  TC2, -TC2);
    cmulc<DIR>(r[7], i[7],  TS1, -TC1);
    cmulc<DIR>(r[9], i[9],  TC2, -TC2);
    mulj<DIR>(r[10],i[10]);
    cmulc<DIR>(r[11],i[11],-TC2, -TC2);
    cmulc<DIR>(r[13],i[13], TS1, -TC1);
    cmulc<DIR>(r[14],i[14],-TC2, -TC2);
    cmulc<DIR>(r[15],i[15],-TC1,  TS1);
    fft4s<DIR>(r[0],i[0], r[4],i[4], r[8], i[8],  r[12],i[12]);
    fft4s<DIR>(r[1],i[1], r[5],i[5], r[9], i[9],  r[13],i[13]);
    fft4s<DIR>(r[2],i[2], r[6],i[6], r[10],i[10], r[14],i[14]);
    fft4s<DIR>(r[3],i[3], r[7],i[7], r[11],i[11], r[15],i[15]);
}

// table twiddles: v[slot(k)] *= w^k, row = &table[idx], k-major stride STRIDE.
// DIR<0 applies the conjugate (negated imaginary part, free in the FFMA).
template<int DIR, int RV, int STRIDE>
__device__ __forceinline__ void twiddle_g(float r[16], float i[16],
                                          const float2* __restrict__ row){
    #pragma unroll
    for (int k = 1; k < 16; ++k){
        const int slot = RV ? REV(k) : k;
        const float2 w = __ldg(row + (k - 1) * STRIDE);
        cmul(r[slot], i[slot], w.x, (DIR < 0) ? -w.y : w.y);
    }
}

#define S1H 258   // half2-entry stride; 258 mod 32 = 2 -> ex1 patterns conflict-free
#define S2H 18    // half2-entry stride; conflict-free W2/R3 (8B paired reads)

__global__ void __launch_bounds__(256, 4) afdf_fft13_kernel(
    const float2* __restrict__ x2,
    const float2* __restrict__ A2,
    const float2* __restrict__ D2,
    float2* __restrict__ out2)
{
    __shared__ __align__(16) __half2 s1h[16 * S1H];    // 16,512 B
    __shared__ __align__(16) __half2 s2h[256 * S2H];   // 18,432 B

    const int t    = threadIdx.x;      // 0..255
    const int c_lo = t & 15;
    const int b2   = t >> 4;           // 0..15
    const size_t base = (size_t)blockIdx.x * 4096;

    const float2* const t1row = g_T1 + t;     // stride 256 (k-major)
    const float2* const t2row = g_T2 + b2;    // stride 16

    float r[16], i[16];

    // ---- load + A scale (elementwise re/im), points m = t + 256*a ----
    #pragma unroll
    for (int a = 0; a < 16; ++a){
        const int n = t + 256 * a;
        const float2 xv = x2[base + n];
        const float2 av = A2[n];
        r[a] = xv.x * av.x;
        i[a] = xv.y * av.y;
    }

    // ================= forward =================
    fft16_nat<-1>(r, i);                                 // U[c] at REV(c)
    twiddle_g<-1, 1, 256>(r, i, t1row);                  // * w4096^{-t c}
    #pragma unroll
    for (int c = 0; c < 16; ++c){
        const int s = REV(c);
        s1h[c * S1H + t] = __floats2half2_rn(r[s], i[s]);
    }
    __syncthreads();                                     // (1)
    #pragma unroll
    for (int a2 = 0; a2 < 16; ++a2){
        const float2 v = __half22float2(s1h[c_lo * S1H + 16 * a2 + b2]);
        r[a2] = v.x; i[a2] = v.y;
    }
    fft16_nat<-1>(r, i);
    twiddle_g<-1, 1, 16>(r, i, t2row);                   // * w256^{-b2 c2}
    #pragma unroll
    for (int c2 = 0; c2 < 16; ++c2){
        const int s = REV(c2);
        s2h[(c2 * 16 + c_lo) * S2H + b2] = __floats2half2_rn(r[s], i[s]);
    }
    __syncthreads();                                     // (2)
    #pragma unroll
    for (int j = 0; j < 8; ++j){
        const uint2 u = *reinterpret_cast<const uint2*>(s2h + t * S2H + 2 * j);
        const float2 v0 = __half22float2(*reinterpret_cast<const __half2*>(&u.x));
        const float2 v1 = __half22float2(*reinterpret_cast<const __half2*>(&u.y));
        r[2*j]   = v0.x; i[2*j]   = v0.y;
        r[2*j+1] = v1.x; i[2*j+1] = v1.y;
    }
    fft16_nat<-1>(r, i);
    // now F[256*d2 + t] sits at slot REV(d2)

    // ---- D scale (1/N folded) ----
    #pragma unroll
    for (int d2 = 0; d2 < 16; ++d2){
        const float2 dv = D2[t + 256 * d2];
        const int s = REV(d2);
        r[s] *= dv.x * INV_N;
        i[s] *= dv.y * INV_N;
    }

    // ================= inverse =================
    fft16_rev<1>(r, i);                                  // REV in -> natural out
    twiddle_g<1, 0, 256>(r, i, t1row);
    // s1 reuse: all ex1 reads happened-before barrier (2)
    #pragma unroll
    for (int c = 0; c < 16; ++c){
        s1h[c * S1H + t] = __floats2half2_rn(r[c], i[c]);
    }
    __syncthreads();                                     // (3)
    #pragma unroll
    for (int a2 = 0; a2 < 16; ++a2){
        const float2 v = __half22float2(s1h[c_lo * S1H + 16 * a2 + b2]);
        r[a2] = v.x; i[a2] = v.y;
    }
    fft16_nat<1>(r, i);
    twiddle_g<1, 1, 16>(r, i, t2row);
    // s2 reuse: stage-3 fwd reads happened-before barrier (3)
    #pragma unroll
    for (int c2 = 0; c2 < 16; ++c2){
        const int s = REV(c2);
        s2h[(c2 * 16 + c_lo) * S2H + b2] = __floats2half2_rn(r[s], i[s]);
    }
    __syncthreads();                                     // (4)
    #pragma unroll
    for (int j = 0; j < 8; ++j){
        const uint2 u = *reinterpret_cast<const uint2*>(s2h + t * S2H + 2 * j);
        const float2 v0 = __half22float2(*reinterpret_cast<const __half2*>(&u.x));
        const float2 v1 = __half22float2(*reinterpret_cast<const __half2*>(&u.y));
        r[2*j]   = v0.x; i[2*j]   = v0.y;
        r[2*j+1] = v1.x; i[2*j+1] = v1.y;
    }
    fft16_nat<1>(r, i);
    // out[256*d2 + t] at slot REV(d2)

    // ---- store ----
    #pragma unroll
    for (int d2 = 0; d2 < 16; ++d2){
        const int s = REV(d2);
        out2[base + t + 256 * d2] = make_float2(r[s], i[s]);
    }
}

extern "C" void kernel_launch(void* const* d_in, const int* in_sizes, int n_in,
                              void* d_out, int out_size)
{
    const float2* x2 = (const float2*)d_in[0];
    const float2* A2 = (const float2*)d_in[1];
    const float2* D2 = (const float2*)d_in[2];
    float2* out2 = (float2*)d_out;

    const int rows = in_sizes[0] / (4096 * 2);
    afdf_twiddle_init<<<1, 256>>>();                 // fill twiddle tables (~2 us)
    afdf_fft13_kernel<<<rows, 256>>>(x2, A2, D2, out2);
}

// round 16
// speedup vs baseline: 1.6568x; 1.6568x over previous
#include <cuda_runtime.h>
#include <cuda_fp16.h>
#include <cstdint>

// out = IFFT( D .* FFT( A .* x ) ) per row, C = 4096, complex as (re,im) float pairs.
// A, D scale re/im independently (elementwise).
//
// 256 threads per row, ONE lane per thread (16 points), 64 regs, ~48% occupancy.
// 4096 = 16^3: three radix-16 register stages; two fp16-staged shared exchanges
// per direction. Twiddles via one __sincosf + odd/even power chains (in-register).
//
// Exchange-1 uses a digit-swapped column layout:
//   entry (c, m) at  c*S1H + 18*(m%16) + (m/16),  S1H = 290
//   write: addr = c*290 + 18*c_lo + b2      -> 32 distinct banks (18c spread)
//   read : addr = c_lo*290 + 18*b2 + a2     -> consecutive in a2 => 8 x LDS.64,
//          8B-bank index = c_lo*145 + 9b2 + j == c_lo + const (mod 16) distinct.
// Exchange-2 identical to the verified R9 pattern (stride 18, paired 8B reads).

#define REV(c) ((((c) & 3) << 2) | ((c) >> 2))

__device__ __forceinline__ void cmul(float& r, float& i, float wr, float wi){
    float t = i * wi;
    float u = i * wr;
    float nr = fmaf(r, wr, -t);
    i = fmaf(r, wi, u);
    r = nr;
}
template<int DIR> __device__ __forceinline__ void mulj(float& r, float& i){
    float t = r;
    if (DIR < 0){ r = i;  i = -t; }
    else        { r = -i; i = t;  }
}
template<int DIR> __device__ __forceinline__ void cmulc(float& r, float& i, float cr, float ci_f){
    cmul(r, i, cr, (DIR < 0) ? ci_f : -ci_f);
}

#define TC1 0.92387953251128674f
#define TS1 0.38268343236508978f
#define TC2 0.70710678118654752f

template<int DIR>
__device__ __forceinline__ void fft4s(float& r0, float& i0, float& r1, float& i1,
                                      float& r2, float& i2, float& r3, float& i3){
    float t0r = r0 + r2, t0i = i0 + i2;
    float t1r = r0 - r2, t1i = i0 - i2;
    float t2r = r1 + r3, t2i = i1 + i3;
    float t3r, t3i;
    if (DIR < 0){ t3r = i1 - i3; t3i = r3 - r1; }
    else        { t3r = i3 - i1; t3i = r1 - r3; }
    r0 = t0r + t2r; i0 = t0i + t2i;
    r2 = t0r - t2r; i2 = t0i - t2i;
    r1 = t1r + t3r; i1 = t1i + t3i;
    r3 = t1r - t3r; i3 = t1i - t3i;
}

template<int DIR>
__device__ __forceinline__ void fft16_nat(float r[16], float i[16]){
    fft4s<DIR>(r[0],i[0], r[4],i[4], r[8], i[8],  r[12],i[12]);
    fft4s<DIR>(r[1],i[1], r[5],i[5], r[9], i[9],  r[13],i[13]);
    fft4s<DIR>(r[2],i[2], r[6],i[6], r[10],i[10], r[14],i[14]);
    fft4s<DIR>(r[3],i[3], r[7],i[7], r[11],i[11], r[15],i[15]);
    cmulc<DIR>(r[5], i[5],  TC1, -TS1);
    cmulc<DIR>(r[9], i[9],  TC2, -TC2);
    cmulc<DIR>(r[13],i[13], TS1, -TC1);
    cmulc<DIR>(r[6], i[6],  TC2, -TC2);
    mulj<DIR>(r[10],i[10]);
    cmulc<DIR>(r[14],i[14],-TC2, -TC2);
    cmulc<DIR>(r[7], i[7],  TS1, -TC1);
    cmulc<DIR>(r[11],i[11],-TC2, -TC2);
    cmulc<DIR>(r[15],i[15],-TC1,  TS1);
    fft4s<DIR>(r[0], i[0],  r[1], i[1],  r[2], i[2],  r[3], i[3]);
    fft4s<DIR>(r[4], i[4],  r[5], i[5],  r[6], i[6],  r[7], i[7]);
    fft4s<DIR>(r[8], i[8],  r[9], i[9],  r[10],i[10], r[11],i[11]);
    fft4s<DIR>(r[12],i[12], r[13],i[13], r[14],i[14], r[15],i[15]);
}

template<int DIR>
__device__ __forceinline__ void fft16_rev(float r[16], float i[16]){
    fft4s<DIR>(r[0], i[0],  r[1], i[1],  r[2], i[2],  r[3], i[3]);
    fft4s<DIR>(r[4], i[4],  r[5], i[5],  r[6], i[6],  r[7], i[7]);
    fft4s<DIR>(r[8], i[8],  r[9], i[9],  r[10],i[10], r[11],i[11]);
    fft4s<DIR>(r[12],i[12], r[13],i[13], r[14],i[14], r[15],i[15]);
    cmulc<DIR>(r[5], i[5],  TC1, -TS1);
    cmulc<DIR>(r[6], i[6],  TC2, -TC2);
    cmulc<DIR>(r[7], i[7],  TS1, -TC1);
    cmulc<DIR>(r[9], i[9],  TC2, -TC2);
    mulj<DIR>(r[10],i[10]);
    cmulc<DIR>(r[11],i[11],-TC2, -TC2);
    cmulc<DIR>(r[13],i[13], TS1, -TC1);
    cmulc<DIR>(r[14],i[14],-TC2, -TC2);
    cmulc<DIR>(r[15],i[15],-TC1,  TS1);
    fft4s<DIR>(r[0],i[0], r[4],i[4], r[8], i[8],  r[12],i[12]);
    fft4s<DIR>(r[1],i[1], r[5],i[5], r[9], i[9],  r[13],i[13]);
    fft4s<DIR>(r[2],i[2], r[6],i[6], r[10],i[10], r[14],i[14]);
    fft4s<DIR>(r[3],i[3], r[7],i[7], r[11],i[11], r[15],i[15]);
}

template<int DIR, int RV>
__device__ __forceinline__ void twiddle_stage(float r[16], float i[16], float theta){
    float sn, cs;
    __sincosf(theta, &sn, &cs);
    if (DIR < 0) sn = -sn;
    float w2r = fmaf(cs, cs, -(sn * sn));
    float w2i = 2.0f * cs * sn;
    float por = cs,  poi = sn;
    float per = w2r, pei = w2i;
    #pragma unroll
    for (int k = 1; k < 16; ++k){
        const int slot = RV ? REV(k) : k;
        if (k & 1){
            cmul(r[slot], i[slot], por, poi);
            if (k + 2 < 16) cmul(por, poi, w2r, w2i);
        } else {
            cmul(r[slot], i[slot], per, pei);
            if (k + 2 < 16) cmul(per, pei, w2r, w2i);
        }
    }
}

#define S1H 290   // half2-entry row stride for ex1 (digit-swapped columns)
#define S2H 18    // half2-entry row stride for ex2
#define D4096 1.5339807878856412e-3f   // 2*pi/4096
#define D256  2.4543692606170259e-2f   // 2*pi/256
#define INV_N (1.0f / 4096.0f)

__global__ void __launch_bounds__(256, 4) afdf_fft16_kernel(
    const float2* __restrict__ x2,
    const float2* __restrict__ A2,
    const float2* __restrict__ D2,
    float2* __restrict__ out2)
{
    __shared__ __align__(16) __half2 s1h[16 * S1H];    // 18,560 B
    __shared__ __align__(16) __half2 s2h[256 * S2H];   // 18,432 B

    const int t    = threadIdx.x;      // 0..255
    const int c_lo = t & 15;
    const int b2   = t >> 4;           // 0..15
    const size_t base = (size_t)blockIdx.x * 4096;

    const int w1off = 18 * c_lo + b2;          // ex1 write column (digit-swapped)
    const int r1off = c_lo * S1H + 18 * b2;    // ex1 read base (pairs in a2)

    float r[16], i[16];

    // ---- load + A scale (elementwise re/im), points m = t + 256*a ----
    #pragma unroll
    for (int a = 0; a < 16; ++a){
        const int n = t + 256 * a;
        const float2 xv = x2[base + n];
        const float2 av = A2[n];
        r[a] = xv.x * av.x;
        i[a] = xv.y * av.y;
    }

    // ================= forward =================
    fft16_nat<-1>(r, i);                                 // U[c] at REV(c)
    twiddle_stage<-1, 1>(r, i, (float)t * D4096);        // * w4096^{-t c}
    #pragma unroll
    for (int c = 0; c < 16; ++c){
        const int s = REV(c);
        s1h[c * S1H + w1off] = __floats2half2_rn(r[s], i[s]);
    }
    __syncthreads();                                     // (1)
    #pragma unroll
    for (int j = 0; j < 8; ++j){
        const uint2 u = *reinterpret_cast<const uint2*>(s1h + r1off + 2 * j);
        const float2 v0 = __half22float2(*reinterpret_cast<const __half2*>(&u.x));
        const float2 v1 = __half22float2(*reinterpret_cast<const __half2*>(&u.y));
        r[2*j]   = v0.x; i[2*j]   = v0.y;
        r[2*j+1] = v1.x; i[2*j+1] = v1.y;
    }
    fft16_nat<-1>(r, i);
    twiddle_stage<-1, 1>(r, i, (float)b2 * D256);        // * w256^{-b2 c2}
    #pragma unroll
    for (int c2 = 0; c2 < 16; ++c2){
        const int s = REV(c2);
        s2h[(c2 * 16 + c_lo) * S2H + b2] = __floats2half2_rn(r[s], i[s]);
    }
    __syncthreads();                                     // (2)
    #pragma unroll
    for (int j = 0; j < 8; ++j){
        const uint2 u = *reinterpret_cast<const uint2*>(s2h + t * S2H + 2 * j);
        const float2 v0 = __half22float2(*reinterpret_cast<const __half2*>(&u.x));
        const float2 v1 = __half22float2(*reinterpret_cast<const __half2*>(&u.y));
        r[2*j]   = v0.x; i[2*j]   = v0.y;
        r[2*j+1] = v1.x; i[2*j+1] = v1.y;
    }
    fft16_nat<-1>(r, i);
    // now F[256*d2 + t] sits at slot REV(d2)

    // ---- D scale (1/N folded) ----
    #pragma unroll
    for (int d2 = 0; d2 < 16; ++d2){
        const float2 dv = D2[t + 256 * d2];
        const int s = REV(d2);
        r[s] *= dv.x * INV_N;
        i[s] *= dv.y * INV_N;
    }

    // ================= inverse =================
    fft16_rev<1>(r, i);                                  // REV in -> natural out
    twiddle_stage<1, 0>(r, i, (float)t * D4096);
    // s1 reuse: all ex1 reads happened-before barrier (2)
    #pragma unroll
    for (int c = 0; c < 16; ++c){
        s1h[c * S1H + w1off] = __floats2half2_rn(r[c], i[c]);
    }
    __syncthreads();                                     // (3)
    #pragma unroll
    for (int j = 0; j < 8; ++j){
        const uint2 u = *reinterpret_cast<const uint2*>(s1h + r1off + 2 * j);
        const float2 v0 = __half22float2(*reinterpret_cast<const __half2*>(&u.x));
        const float2 v1 = __half22float2(*reinterpret_cast<const __half2*>(&u.y));
        r[2*j]   = v0.x; i[2*j]   = v0.y;
        r[2*j+1] = v1.x; i[2*j+1] = v1.y;
    }
    fft16_nat<1>(r, i);
    twiddle_stage<1, 1>(r, i, (float)b2 * D256);
    // s2 reuse: stage-3 fwd reads happened-before barrier (3)
    #pragma unroll
    for (int c2 = 0; c2 < 16; ++c2){
        const int s = REV(c2);
        s2h[(c2 * 16 + c_lo) * S2H + b2] = __floats2half2_rn(r[s], i[s]);
    }
    __syncthreads();                                     // (4)
    #pragma unroll
    for (int j = 0; j < 8; ++j){
        const uint2 u = *reinterpret_cast<const uint2*>(s2h + t * S2H + 2 * j);
        const float2 v0 = __half22float2(*reinterpret_cast<const __half2*>(&u.x));
        const float2 v1 = __half22float2(*reinterpret_cast<const __half2*>(&u.y));
        r[2*j]   = v0.x; i[2*j]   = v0.y;
        r[2*j+1] = v1.x; i[2*j+1] = v1.y;
    }
    fft16_nat<1>(r, i);
    // out[256*d2 + t] at slot REV(d2)

    // ---- store ----
    #pragma unroll
    for (int d2 = 0; d2 < 16; ++d2){
        const int s = REV(d2);
        out2[base + t + 256 * d2] = make_float2(r[s], i[s]);
    }
}

extern "C" void kernel_launch(void* const* d_in, const int* in_sizes, int n_in,
                              void* d_out, int out_size)
{
    const float2* x2 = (const float2*)d_in[0];
    const float2* A2 = (const float2*)d_in[1];
    const float2* D2 = (const float2*)d_in[2];
    float2* out2 = (float2*)d_out;

    const int rows = in_sizes[0] / (4096 * 2);
    afdf_fft16_kernel<<<rows, 256>>>(x2, A2, D2, out2);
}